// round 5
// baseline (speedup 1.0000x reference)
#include <cuda_runtime.h>
#include <math.h>

#define BB 8
#define NN 256
#define DD 128
#define ROWS (BB*NN)          // 2048
#define EROWS (BB*NN*NN)      // 524288
#define BN_EPS 1e-5f
#define RPW 8                 // e-rows per warp in copy role
#define TI  8                 // i-rows per fused block

#define NB_COPY  8192         // 64 e-rows each (8 warps x 8 rows)
#define NB_FUSED 256          // 8 i-rows each
#define NB_BN    256          // 8 h-rows each (warp per row)
#define NB_TOTAL (NB_COPY + NB_FUSED + NB_BN)
#define CHUNKS_PER_BATCH 1024 // copy blocks per batch

// scratch (allocation-free rule: __device__ globals; zero-init at load,
// self-reset at end of every launch -> graph-replay safe)
__device__ float g_w[EROWS];
__device__ float g_h1[ROWS*DD];
__device__ float g_sum[DD];
__device__ float g_sumsq[DD];
__device__ int   g_done[BB];
__device__ int   g_fused_done;
__device__ int   g_bn_done;

__device__ __forceinline__ void spin_until(int* cnt, int target) {
    if (threadIdx.x == 0) {
        while (atomicAdd(cnt, 0) < target) __nanosleep(128);
    }
    __syncthreads();
    __threadfence();
}

__global__ void __launch_bounds__(256) k_mega(
    const float* __restrict__ h,
    const float4* __restrict__ e4,
    const float* __restrict__ Wm,
    const float* __restrict__ bias,
    const float* __restrict__ gamma,
    const float* __restrict__ beta,
    float* __restrict__ out_h,
    float4* __restrict__ out_e4)
{
    int bid = blockIdx.x;
    int tid = threadIdx.x;

    // ======================= ROLE A: norm + copy ==========================
    if (bid < NB_COPY) {
        size_t gw   = (size_t)bid * 8 + (tid >> 5);   // global warp id
        int    lane = tid & 31;
        size_t r0   = gw * RPW;
        size_t base = r0 * 32 + lane;

        float4 v[RPW];
        #pragma unroll
        for (int k = 0; k < RPW; k++)
            v[k] = __ldcs(e4 + base + (size_t)k * 32);
        #pragma unroll
        for (int k = 0; k < RPW; k++)
            __stcs(out_e4 + base + (size_t)k * 32, v[k]);

        float s[RPW];
        #pragma unroll
        for (int k = 0; k < RPW; k++)
            s[k] = v[k].x*v[k].x + v[k].y*v[k].y + v[k].z*v[k].z + v[k].w*v[k].w;
        #pragma unroll
        for (int o = 16; o > 0; o >>= 1) {
            #pragma unroll
            for (int k = 0; k < RPW; k++)
                s[k] += __shfl_xor_sync(0xffffffffu, s[k], o);
        }
        if (lane == 0) {
            #pragma unroll
            for (int k = 0; k < RPW; k++)
                g_w[r0 + k] = sqrtf(s[k]);
        }
        __syncthreads();
        if (tid == 0) {
            __threadfence();
            atomicAdd(&g_done[bid >> 10], 1);   // 1024 chunks per batch
        }
        return;
    }

    // ================= ROLE B: softmax + agg + linear + stats =============
    if (bid < NB_COPY + NB_FUSED) {
        int idx = bid - NB_COPY;          // 0..255
        int bi0 = idx * TI;
        int b   = bi0 >> 8;
        int i0  = bi0 & 255;

        spin_until(&g_done[b], CHUNKS_PER_BATCH);

        __shared__ float sw[TI][NN];      // softmax probs
        __shared__ float sx[TI][DD];      // pre-linear activations
        __shared__ float pp[DD], pps[DD]; // half-1 partial BN sums

        int warp = tid >> 5, lane = tid & 31;

        // softmax: warp r owns row r
        {
            const float* wrow = g_w + (size_t)(bi0 + warp) * NN;
            float v[NN/32];
            float m = -1e30f;
            #pragma unroll
            for (int k = 0; k < NN/32; k++) {
                v[k] = wrow[lane + 32*k];
                m = fmaxf(m, v[k]);
            }
            #pragma unroll
            for (int o = 16; o > 0; o >>= 1)
                m = fmaxf(m, __shfl_xor_sync(0xffffffffu, m, o));
            float sum = 0.0f;
            #pragma unroll
            for (int k = 0; k < NN/32; k++) {
                v[k] = __expf(v[k] - m);
                sum += v[k];
            }
            #pragma unroll
            for (int o = 16; o > 0; o >>= 1)
                sum += __shfl_xor_sync(0xffffffffu, sum, o);
            float inv = 1.0f / sum;
            #pragma unroll
            for (int k = 0; k < NN/32; k++)
                sw[warp][lane + 32*k] = v[k] * inv;
        }
        __syncthreads();

        // aggregation: thread = (half, feature); half owns 4 rows
        int t    = tid & 127;
        int half = tid >> 7;              // 0 or 1
        const float* hb = h + (size_t)b * NN * DD;
        float acc[4] = {0.f, 0.f, 0.f, 0.f};

        for (int j0 = 0; j0 < NN; j0 += 16) {
            float hv[16];
            #pragma unroll
            for (int k = 0; k < 16; k++)
                hv[k] = hb[(j0 + k) * DD + t];
            #pragma unroll
            for (int r = 0; r < 4; r++) {
                const float4* swr = (const float4*)&sw[half*4 + r][j0];
                #pragma unroll
                for (int q = 0; q < 4; q++) {
                    float4 p = swr[q];
                    acc[r] = fmaf(p.x, hv[q*4+0], acc[r]);
                    acc[r] = fmaf(p.y, hv[q*4+1], acc[r]);
                    acc[r] = fmaf(p.z, hv[q*4+2], acc[r]);
                    acc[r] = fmaf(p.w, hv[q*4+3], acc[r]);
                }
            }
        }
        #pragma unroll
        for (int r = 0; r < 4; r++)
            sx[half*4 + r][t] = hb[(i0 + half*4 + r) * DD + t] + acc[r];
        __syncthreads();

        // linear + relu
        float y[4];
        float bt = bias[t];
        #pragma unroll
        for (int r = 0; r < 4; r++) y[r] = bt;

        const float4* wr = (const float4*)(Wm + (size_t)t * DD);
        #pragma unroll 4
        for (int d4 = 0; d4 < DD/4; d4++) {
            float4 wv = __ldg(wr + d4);
            #pragma unroll
            for (int r = 0; r < 4; r++) {
                const float4 xv = ((const float4*)sx[half*4 + r])[d4];
                y[r] = fmaf(wv.x, xv.x, y[r]);
                y[r] = fmaf(wv.y, xv.y, y[r]);
                y[r] = fmaf(wv.z, xv.z, y[r]);
                y[r] = fmaf(wv.w, xv.w, y[r]);
            }
        }

        float ls = 0.0f, lss = 0.0f;
        #pragma unroll
        for (int r = 0; r < 4; r++) {
            float yy = fmaxf(y[r], 0.0f);
            g_h1[(bi0 + half*4 + r) * DD + t] = yy;
            ls  += yy;
            lss  = fmaf(yy, yy, lss);
        }
        // combine halves in smem -> one atomic pair per feature
        if (half == 1) { pp[t] = ls; pps[t] = lss; }
        __syncthreads();
        if (half == 0) {
            atomicAdd(&g_sum[t],   ls  + pp[t]);
            atomicAdd(&g_sumsq[t], lss + pps[t]);
        }
        __syncthreads();
        if (tid == 0) {
            __threadfence();
            atomicAdd(&g_fused_done, 1);
        }
        return;
    }

    // =================== ROLE C: BN apply + residual ======================
    {
        int idx = bid - NB_COPY - NB_FUSED;  // 0..255
        spin_until(&g_fused_done, NB_FUSED);

        int warp = tid >> 5, lane = tid & 31;
        int row  = idx * 8 + warp;

        float4 s  = ((const float4*)g_sum)[lane];
        float4 ss = ((const float4*)g_sumsq)[lane];
        float4 gm = ((const float4*)gamma)[lane];
        float4 bb = ((const float4*)beta)[lane];

        const float inv = 1.0f / ROWS;
        float mx = s.x*inv, my = s.y*inv, mz = s.z*inv, mw = s.w*inv;
        float gx = gm.x * rsqrtf(ss.x*inv - mx*mx + BN_EPS);
        float gy = gm.y * rsqrtf(ss.y*inv - my*my + BN_EPS);
        float gz = gm.z * rsqrtf(ss.z*inv - mz*mz + BN_EPS);
        float gw = gm.w * rsqrtf(ss.w*inv - mw*mw + BN_EPS);
        float bx = bb.x - mx*gx, by = bb.y - my*gy;
        float bz = bb.z - mz*gz, bw = bb.w - mw*gw;

        int o = row * 32 + lane;
        float4 v  = ((const float4*)g_h1)[o];
        float4 hv = ((const float4*)h)[o];
        float4 r4;
        r4.x = fmaf(v.x, gx, bx) + hv.x;
        r4.y = fmaf(v.y, gy, by) + hv.y;
        r4.z = fmaf(v.z, gz, bz) + hv.z;
        r4.w = fmaf(v.w, gw, bw) + hv.w;
        ((float4*)out_h)[o] = r4;

        __syncthreads();
        if (tid == 0) {
            int old = atomicAdd(&g_bn_done, 1);
            if (old == NB_BN - 1) {
                // last block: reset all inter-launch state for next replay
                #pragma unroll
                for (int k = 0; k < BB; k++) g_done[k] = 0;
                g_fused_done = 0;
                g_bn_done    = 0;
                #pragma unroll 4
                for (int k = 0; k < DD; k++) { g_sum[k] = 0.0f; g_sumsq[k] = 0.0f; }
                __threadfence();
            }
        }
    }
}

// ---------------------------------------------------------------------------
extern "C" void kernel_launch(void* const* d_in, const int* in_sizes, int n_in,
                              void* d_out, int out_size) {
    const float* h     = (const float*)d_in[0];   // (8,256,128)
    const float* e     = (const float*)d_in[1];   // (8,256,256,128)
    const float* Wm    = (const float*)d_in[2];   // (128,128)
    const float* bias  = (const float*)d_in[3];   // (128)
    const float* gamma = (const float*)d_in[4];   // (128)
    const float* beta  = (const float*)d_in[5];   // (128)

    float* out_h = (float*)d_out;                 // (8,256,128) first
    float* out_e = out_h + (size_t)ROWS * DD;     // then (8,256,256,128)

    k_mega<<<NB_TOTAL, 256>>>(h, (const float4*)e, Wm, bias, gamma, beta,
                              out_h, (float4*)out_e);
}

// round 7
// speedup vs baseline: 1.1080x; 1.1080x over previous
#include <cuda_runtime.h>
#include <math.h>

#define BB 8
#define NN 256
#define DD 128
#define ROWS (BB*NN)          // 2048
#define EROWS (BB*NN*NN)      // 524288
#define BN_EPS 1e-5f
#define RPW 8                 // e-rows per warp in copy kernel
#define TI  4                 // i-rows per tail block
#define NB_TAIL (ROWS/TI)     // 512 tail blocks

#define NB_COPY  8192         // copy blocks (64 e-rows each)

// __device__ globals (zero at load; reset each launch by copy kernel block 0,
// which is stream-ordered before the tail kernel -> graph-replay safe)
__device__ float g_w[EROWS];
__device__ float g_sum[DD];
__device__ float g_sumsq[DD];
__device__ int   g_barrier;

// ---------------------------------------------------------------------------
// Kernel 1: norm + copy of e. Measured 6.4 TB/s (80% of spec) — hot path
// untouched. Block 0 additionally resets the tail's inter-launch state.
// ---------------------------------------------------------------------------
__global__ void __launch_bounds__(256) k_norm_copy(
    const float4* __restrict__ e,
    float4* __restrict__ out_e)
{
    if (blockIdx.x == 0 && threadIdx.x < DD) {
        g_sum[threadIdx.x]   = 0.0f;
        g_sumsq[threadIdx.x] = 0.0f;
        if (threadIdx.x == 0) g_barrier = 0;
    }
    size_t gw   = (size_t)((blockIdx.x * blockDim.x + threadIdx.x) >> 5);
    int    lane = threadIdx.x & 31;
    size_t r0   = gw * RPW;
    size_t base = r0 * 32 + lane;

    float4 v[RPW];
    #pragma unroll
    for (int k = 0; k < RPW; k++)
        v[k] = __ldcs(e + base + (size_t)k * 32);
    #pragma unroll
    for (int k = 0; k < RPW; k++)
        __stcs(out_e + base + (size_t)k * 32, v[k]);

    float s[RPW];
    #pragma unroll
    for (int k = 0; k < RPW; k++)
        s[k] = v[k].x*v[k].x + v[k].y*v[k].y + v[k].z*v[k].z + v[k].w*v[k].w;
    #pragma unroll
    for (int o = 16; o > 0; o >>= 1) {
        #pragma unroll
        for (int k = 0; k < RPW; k++)
            s[k] += __shfl_xor_sync(0xffffffffu, s[k], o);
    }
    if (lane == 0) {
        #pragma unroll
        for (int k = 0; k < RPW; k++)
            g_w[r0 + k] = sqrtf(s[k]);
    }
}

// ---------------------------------------------------------------------------
// Kernel 2: the ENTIRE tail in one launch.
// Block = 128 threads handles TI=4 consecutive i-rows of one batch:
//   softmax (1 row per warp) -> agg (reg accs) -> linear+relu (y in regs)
//   -> BN stat atomics -> intra-kernel grid barrier -> BN apply + residual.
// 512 blocks are provably co-resident (>=10 blocks/SM fit), so the spin
// barrier cannot deadlock, and it's all one kernel (ncu-replay safe).
// ---------------------------------------------------------------------------
__global__ void __launch_bounds__(128) k_tail_all(
    const float* __restrict__ h,
    const float* __restrict__ Wm,
    const float* __restrict__ bias,
    const float* __restrict__ gamma,
    const float* __restrict__ beta,
    float* __restrict__ out_h)
{
    int bi0 = blockIdx.x * TI;
    int b   = bi0 >> 8;
    int i0  = bi0 & 255;
    int t   = threadIdx.x;
    int warp = t >> 5, lane = t & 31;

    __shared__ float sw[TI][NN];     // softmax probs (4 KB)
    __shared__ float sx[TI][DD];     // pre-linear activations (2 KB)

    // --- softmax: warp r owns row r (shuffle reductions only) ---
    {
        const float* wrow = g_w + (size_t)(bi0 + warp) * NN;
        float v[NN/32];
        float m = -1e30f;
        #pragma unroll
        for (int k = 0; k < NN/32; k++) {
            v[k] = wrow[lane + 32*k];
            m = fmaxf(m, v[k]);
        }
        #pragma unroll
        for (int o = 16; o > 0; o >>= 1)
            m = fmaxf(m, __shfl_xor_sync(0xffffffffu, m, o));
        float sum = 0.0f;
        #pragma unroll
        for (int k = 0; k < NN/32; k++) {
            v[k] = __expf(v[k] - m);
            sum += v[k];
        }
        #pragma unroll
        for (int o = 16; o > 0; o >>= 1)
            sum += __shfl_xor_sync(0xffffffffu, sum, o);
        float inv = 1.0f / sum;
        #pragma unroll
        for (int k = 0; k < NN/32; k++)
            sw[warp][lane + 32*k] = v[k] * inv;
    }
    __syncthreads();

    // --- aggregation: 16-deep LDG batches, 4 reg accumulators ---
    const float* hb = h + (size_t)b * NN * DD;
    float acc[TI] = {0.f, 0.f, 0.f, 0.f};

    for (int j0 = 0; j0 < NN; j0 += 16) {
        float hv[16];
        #pragma unroll
        for (int k = 0; k < 16; k++)
            hv[k] = hb[(j0 + k) * DD + t];
        #pragma unroll
        for (int r = 0; r < TI; r++) {
            const float4* swr = (const float4*)&sw[r][j0];
            #pragma unroll
            for (int q = 0; q < 4; q++) {
                float4 p = swr[q];
                acc[r] = fmaf(p.x, hv[q*4+0], acc[r]);
                acc[r] = fmaf(p.y, hv[q*4+1], acc[r]);
                acc[r] = fmaf(p.z, hv[q*4+2], acc[r]);
                acc[r] = fmaf(p.w, hv[q*4+3], acc[r]);
            }
        }
    }
    float hres[TI];                  // residual values stay in registers
    #pragma unroll
    for (int r = 0; r < TI; r++) {
        hres[r] = hb[(i0 + r) * DD + t];
        sx[r][t] = hres[r] + acc[r];
    }
    __syncthreads();

    // --- linear + relu, y[] stays in registers ---
    float y[TI];
    float bt = bias[t];
    #pragma unroll
    for (int r = 0; r < TI; r++) y[r] = bt;

    const float4* wr = (const float4*)(Wm + (size_t)t * DD);
    #pragma unroll 8
    for (int d4 = 0; d4 < DD/4; d4++) {
        float4 wv = __ldg(wr + d4);
        #pragma unroll
        for (int r = 0; r < TI; r++) {
            const float4 xv = ((const float4*)sx[r])[d4];
            y[r] = fmaf(wv.x, xv.x, y[r]);
            y[r] = fmaf(wv.y, xv.y, y[r]);
            y[r] = fmaf(wv.z, xv.z, y[r]);
            y[r] = fmaf(wv.w, xv.w, y[r]);
        }
    }

    float ls = 0.0f, lss = 0.0f;
    #pragma unroll
    for (int r = 0; r < TI; r++) {
        y[r] = fmaxf(y[r], 0.0f);
        ls  += y[r];
        lss  = fmaf(y[r], y[r], lss);
    }
    atomicAdd(&g_sum[t],   ls);
    atomicAdd(&g_sumsq[t], lss);

    // --- intra-kernel grid barrier (all 512 blocks co-resident) ---
    __syncthreads();
    if (t == 0) {
        __threadfence();
        atomicAdd(&g_barrier, 1);
        while (atomicAdd(&g_barrier, 0) < NB_TAIL) __nanosleep(64);
    }
    __syncthreads();
    __threadfence();

    // --- BN apply + residual straight from registers ---
    float s  = g_sum[t];
    float ss = g_sumsq[t];
    float mean = s * (1.0f / ROWS);
    float var  = ss * (1.0f / ROWS) - mean * mean;
    float g  = gamma[t] * rsqrtf(var + BN_EPS);
    float b2 = beta[t] - mean * g;
    #pragma unroll
    for (int r = 0; r < TI; r++)
        out_h[(bi0 + r) * DD + t] = fmaf(y[r], g, b2) + hres[r];
}

// ---------------------------------------------------------------------------
extern "C" void kernel_launch(void* const* d_in, const int* in_sizes, int n_in,
                              void* d_out, int out_size) {
    const float* h     = (const float*)d_in[0];   // (8,256,128)
    const float* e     = (const float*)d_in[1];   // (8,256,256,128)
    const float* Wm    = (const float*)d_in[2];   // (128,128)
    const float* bias  = (const float*)d_in[3];   // (128)
    const float* gamma = (const float*)d_in[4];   // (128)
    const float* beta  = (const float*)d_in[5];   // (128)

    float* out_h = (float*)d_out;                 // (8,256,128) first
    float* out_e = out_h + (size_t)ROWS * DD;     // then (8,256,256,128)

    k_norm_copy<<<NB_COPY, 256>>>((const float4*)e, (float4*)out_e);
    k_tail_all<<<NB_TAIL, 128>>>(h, Wm, bias, gamma, beta, out_h);
}

// round 8
// speedup vs baseline: 1.1567x; 1.0439x over previous
#include <cuda_runtime.h>
#include <math.h>

#define BB 8
#define NN 256
#define DD 128
#define ROWS (BB*NN)          // 2048
#define EROWS (BB*NN*NN)      // 524288
#define BN_EPS 1e-5f
#define RPW 8                 // e-rows per warp in copy kernel
#define TI  4                 // i-rows per tail block
#define NB_TAIL (ROWS/TI)     // 512 tail blocks
#define NB_COPY  8192         // copy blocks (64 e-rows each)

// __device__ globals (zero at load; reset each launch by copy kernel block 0,
// stream-ordered before the tail kernel -> graph-replay safe)
__device__ float g_w[EROWS];
__device__ float g_Wt[DD*DD];         // W transposed: g_Wt[d*128+t] = W[t][d]
__device__ float g_sum[DD];
__device__ float g_sumsq[DD];
__device__ int   g_barrier;

// ---------------------------------------------------------------------------
// Kernel 1: norm + copy of e (6.4 TB/s hot path untouched). Block 0 also
// resets tail state and transposes W into g_Wt (hidden under 8191 blocks).
// ---------------------------------------------------------------------------
__global__ void __launch_bounds__(256) k_norm_copy(
    const float4* __restrict__ e,
    float4* __restrict__ out_e,
    const float* __restrict__ Wm)
{
    if (blockIdx.x == 0) {
        if (threadIdx.x < DD) {
            g_sum[threadIdx.x]   = 0.0f;
            g_sumsq[threadIdx.x] = 0.0f;
            if (threadIdx.x == 0) g_barrier = 0;
        }
        // transpose W: 16384 elems, 64 per thread
        for (int i = threadIdx.x; i < DD*DD; i += 256) {
            int t = i >> 7, d = i & 127;          // read W row-major, coalesced
            g_Wt[d * DD + t] = Wm[i];
        }
    }
    size_t gw   = (size_t)((blockIdx.x * blockDim.x + threadIdx.x) >> 5);
    int    lane = threadIdx.x & 31;
    size_t r0   = gw * RPW;
    size_t base = r0 * 32 + lane;

    float4 v[RPW];
    #pragma unroll
    for (int k = 0; k < RPW; k++)
        v[k] = __ldcs(e + base + (size_t)k * 32);
    #pragma unroll
    for (int k = 0; k < RPW; k++)
        __stcs(out_e + base + (size_t)k * 32, v[k]);

    float s[RPW];
    #pragma unroll
    for (int k = 0; k < RPW; k++)
        s[k] = v[k].x*v[k].x + v[k].y*v[k].y + v[k].z*v[k].z + v[k].w*v[k].w;
    #pragma unroll
    for (int o = 16; o > 0; o >>= 1) {
        #pragma unroll
        for (int k = 0; k < RPW; k++)
            s[k] += __shfl_xor_sync(0xffffffffu, s[k], o);
    }
    if (lane == 0) {
        #pragma unroll
        for (int k = 0; k < RPW; k++)
            g_w[r0 + k] = sqrtf(s[k]);
    }
}

// ---------------------------------------------------------------------------
// Kernel 2: entire tail, 512 blocks x 256 threads (27.7 warps/SM).
//   t = tid&127 (feature), half = tid>>7 (j-split in agg; row-split after).
//   softmax (warps 0-3) -> agg (halves split j, smem combine) ->
//   linear via coalesced g_Wt -> BN atomics -> grid barrier -> BN apply.
// ---------------------------------------------------------------------------
__global__ void __launch_bounds__(256) k_tail_all(
    const float* __restrict__ h,
    const float* __restrict__ bias,
    const float* __restrict__ gamma,
    const float* __restrict__ beta,
    float* __restrict__ out_h)
{
    int bi0 = blockIdx.x * TI;
    int b   = bi0 >> 8;
    int i0  = bi0 & 255;
    int tid = threadIdx.x;
    int t    = tid & 127;
    int half = tid >> 7;
    int warp = tid >> 5, lane = tid & 31;

    __shared__ float sw[TI][NN];        // softmax probs (4 KB)
    __shared__ float sacc[2][TI][DD];   // per-half partial aggs (4 KB)
    __shared__ float sx[TI][DD];        // pre-linear activations (2 KB)
    __shared__ float pp[DD], pps[DD];   // half-1 BN partials

    // --- softmax: warps 0-3, one row each ---
    if (warp < TI) {
        const float* wrow = g_w + (size_t)(bi0 + warp) * NN;
        float v[NN/32];
        float m = -1e30f;
        #pragma unroll
        for (int k = 0; k < NN/32; k++) {
            v[k] = wrow[lane + 32*k];
            m = fmaxf(m, v[k]);
        }
        #pragma unroll
        for (int o = 16; o > 0; o >>= 1)
            m = fmaxf(m, __shfl_xor_sync(0xffffffffu, m, o));
        float sum = 0.0f;
        #pragma unroll
        for (int k = 0; k < NN/32; k++) {
            v[k] = __expf(v[k] - m);
            sum += v[k];
        }
        #pragma unroll
        for (int o = 16; o > 0; o >>= 1)
            sum += __shfl_xor_sync(0xffffffffu, sum, o);
        float inv = 1.0f / sum;
        #pragma unroll
        for (int k = 0; k < NN/32; k++)
            sw[warp][lane + 32*k] = v[k] * inv;
    }
    __syncthreads();

    // --- aggregation: half owns j in [half*128, half*128+128) for ALL 4 rows ---
    const float* hb = h + (size_t)b * NN * DD;
    {
        float acc[TI] = {0.f, 0.f, 0.f, 0.f};
        int jbase = half * 128;
        for (int j0 = 0; j0 < 128; j0 += 16) {
            float hv[16];
            #pragma unroll
            for (int k = 0; k < 16; k++)
                hv[k] = hb[(jbase + j0 + k) * DD + t];
            #pragma unroll
            for (int r = 0; r < TI; r++) {
                const float4* swr = (const float4*)&sw[r][jbase + j0];
                #pragma unroll
                for (int q = 0; q < 4; q++) {
                    float4 p = swr[q];
                    acc[r] = fmaf(p.x, hv[q*4+0], acc[r]);
                    acc[r] = fmaf(p.y, hv[q*4+1], acc[r]);
                    acc[r] = fmaf(p.z, hv[q*4+2], acc[r]);
                    acc[r] = fmaf(p.w, hv[q*4+3], acc[r]);
                }
            }
        }
        #pragma unroll
        for (int r = 0; r < TI; r++)
            sacc[half][r][t] = acc[r];
    }
    __syncthreads();

    // --- combine halves; half owns rows {2*half, 2*half+1} from here on ---
    float hres[2];
    #pragma unroll
    for (int rr = 0; rr < 2; rr++) {
        int r = half * 2 + rr;
        hres[rr] = hb[(i0 + r) * DD + t];
        sx[r][t] = hres[rr] + sacc[0][r][t] + sacc[1][r][t];
    }
    __syncthreads();

    // --- linear via transposed W (coalesced): y[rr] = bias + sum_d sx*WT ---
    float y[2];
    float bt = bias[t];
    y[0] = bt; y[1] = bt;

    for (int d0 = 0; d0 < DD; d0 += 16) {
        float wt[16];
        #pragma unroll
        for (int k = 0; k < 16; k++)
            wt[k] = g_Wt[(d0 + k) * DD + t];    // coalesced, L1-hot
        #pragma unroll
        for (int rr = 0; rr < 2; rr++) {
            const float4* xr = (const float4*)&sx[half*2 + rr][d0];
            #pragma unroll
            for (int q = 0; q < 4; q++) {
                float4 xv = xr[q];
                y[rr] = fmaf(xv.x, wt[q*4+0], y[rr]);
                y[rr] = fmaf(xv.y, wt[q*4+1], y[rr]);
                y[rr] = fmaf(xv.z, wt[q*4+2], y[rr]);
                y[rr] = fmaf(xv.w, wt[q*4+3], y[rr]);
            }
        }
    }

    float ls = 0.0f, lss = 0.0f;
    #pragma unroll
    for (int rr = 0; rr < 2; rr++) {
        y[rr] = fmaxf(y[rr], 0.0f);
        ls  += y[rr];
        lss  = fmaf(y[rr], y[rr], lss);
    }
    // combine halves in smem -> one atomic pair per feature per block
    if (half == 1) { pp[t] = ls; pps[t] = lss; }
    __syncthreads();
    if (half == 0) {
        atomicAdd(&g_sum[t],   ls  + pp[t]);
        atomicAdd(&g_sumsq[t], lss + pps[t]);
        __threadfence();
    }

    // --- grid barrier (512 blocks co-resident by construction) ---
    __syncthreads();
    if (tid == 0) {
        __threadfence();
        atomicAdd(&g_barrier, 1);
        while (atomicAdd(&g_barrier, 0) < NB_TAIL) __nanosleep(64);
    }
    __syncthreads();
    __threadfence();

    // --- BN apply + residual straight from registers ---
    float s  = __ldcg(&g_sum[t]);
    float ss = __ldcg(&g_sumsq[t]);
    float mean = s * (1.0f / ROWS);
    float var  = ss * (1.0f / ROWS) - mean * mean;
    float g  = gamma[t] * rsqrtf(var + BN_EPS);
    float b2 = beta[t] - mean * g;
    #pragma unroll
    for (int rr = 0; rr < 2; rr++) {
        int r = half * 2 + rr;
        out_h[(bi0 + r) * DD + t] = fmaf(y[rr], g, b2) + hres[rr];
    }
}

// ---------------------------------------------------------------------------
extern "C" void kernel_launch(void* const* d_in, const int* in_sizes, int n_in,
                              void* d_out, int out_size) {
    const float* h     = (const float*)d_in[0];   // (8,256,128)
    const float* e     = (const float*)d_in[1];   // (8,256,256,128)
    const float* Wm    = (const float*)d_in[2];   // (128,128)
    const float* bias  = (const float*)d_in[3];   // (128)
    const float* gamma = (const float*)d_in[4];   // (128)
    const float* beta  = (const float*)d_in[5];   // (128)

    float* out_h = (float*)d_out;                 // (8,256,128) first
    float* out_e = out_h + (size_t)ROWS * DD;     // then (8,256,256,128)

    k_norm_copy<<<NB_COPY, 256>>>((const float4*)e, (float4*)out_e, Wm);
    k_tail_all<<<NB_TAIL, 256>>>(h, bias, gamma, beta, out_h);
}